// round 2
// baseline (speedup 1.0000x reference)
#include <cuda_runtime.h>
#include <cuda_bf16.h>
#include <math.h>

// Problem constants
#define NSEG   4096
#define NVOT   1048576
#define NCAND  32
#define EMB    128

#define TM      128      // voters per CTA tile
#define THREADS 256
#define SX_STRIDE 36     // padded stride for x tile (avoid bank conflicts)
#define SH_STRIDE 132    // padded stride for h tiles

// Scratch for segment sums (allocation-free rule: __device__ global array)
__device__ float g_agg[NSEG * EMB];

// smem layout (floats): sW[128*128] | sA[128*132] | sB[128*132] | sX[128*36]
#define SW_ELEMS (128*128)
#define SH_ELEMS (128*SH_STRIDE)
#define SX_ELEMS (128*SX_STRIDE)
#define SMEM_FLOATS (SW_ELEMS + 2*SH_ELEMS + SX_ELEMS)
#define SMEM_BYTES (SMEM_FLOATS * 4)

__global__ void zero_agg_kernel() {
    int i = blockIdx.x * blockDim.x + threadIdx.x;
    if (i < NSEG * EMB) g_agg[i] = 0.0f;
}

// Register-tiled 128x128(xK) MMA over shared tiles.
// A: [128 rows x K], row stride ASTRIDE. B: [K x 128], row stride 128.
template <int K, int ASTRIDE>
__device__ __forceinline__ void tile_mma(const float* __restrict__ A,
                                         const float* __restrict__ B,
                                         float acc[8][8], int r0, int c0) {
#pragma unroll 4
    for (int k = 0; k < K; ++k) {
        float a[8];
#pragma unroll
        for (int i = 0; i < 8; ++i) a[i] = A[(r0 + i) * ASTRIDE + k];
        float4 b0 = *reinterpret_cast<const float4*>(B + k * 128 + c0);
        float4 b1 = *reinterpret_cast<const float4*>(B + k * 128 + c0 + 4);
        float b[8] = {b0.x, b0.y, b0.z, b0.w, b1.x, b1.y, b1.z, b1.w};
#pragma unroll
        for (int i = 0; i < 8; ++i)
#pragma unroll
            for (int j = 0; j < 8; ++j)
                acc[i][j] += a[i] * b[j];
    }
}

__global__ __launch_bounds__(THREADS, 1)
void local_mlp_kernel(const float* __restrict__ x, const int* __restrict__ index,
                      const float* __restrict__ lW1, const float* __restrict__ lb1,
                      const float* __restrict__ lW2, const float* __restrict__ lb2,
                      const float* __restrict__ lW3, const float* __restrict__ lb3) {
    extern __shared__ float sm[];
    float* sW = sm;                       // current layer weight (row-major [K,128])
    float* sA = sW + SW_ELEMS;            // h buffer A (stride 132)
    float* sB = sA + SH_ELEMS;            // h buffer B (stride 132)
    float* sX = sB + SH_ELEMS;            // x tile (stride 36)
    __shared__ float sBias[EMB];
    __shared__ int   sIdx[TM];

    const int tid = threadIdx.x;
    const long long v0 = (long long)blockIdx.x * TM;

    // ---- stage x tile + W1 + b1 + indices ----
    {
        const float4* xg = reinterpret_cast<const float4*>(x + v0 * NCAND);
        for (int t = tid; t < TM * NCAND / 4; t += THREADS) {
            float4 v = xg[t];
            int row = t >> 3;          // 8 float4 per 32-wide row
            int c4  = (t & 7) * 4;
            float* dst = sX + row * SX_STRIDE + c4;
            dst[0] = v.x; dst[1] = v.y; dst[2] = v.z; dst[3] = v.w;
        }
        const float4* wg = reinterpret_cast<const float4*>(lW1);
        float4* ws = reinterpret_cast<float4*>(sW);
        for (int t = tid; t < NCAND * EMB / 4; t += THREADS) ws[t] = wg[t];
        if (tid < EMB) sBias[tid] = lb1[tid];
        if (tid < TM)  sIdx[tid]  = index[v0 + tid];
    }
    __syncthreads();

    const int ty = tid >> 4, tx = tid & 15;
    const int r0 = ty * 8, c0 = tx * 8;
    float acc[8][8];

    // ---- layer 1: relu(x @ W1 + b1) -> sA ----
#pragma unroll
    for (int i = 0; i < 8; ++i)
#pragma unroll
        for (int j = 0; j < 8; ++j) acc[i][j] = 0.0f;
    tile_mma<NCAND, SX_STRIDE>(sX, sW, acc, r0, c0);
#pragma unroll
    for (int i = 0; i < 8; ++i)
#pragma unroll
        for (int j = 0; j < 8; ++j)
            sA[(r0 + i) * SH_STRIDE + c0 + j] = fmaxf(acc[i][j] + sBias[c0 + j], 0.0f);
    __syncthreads();

    // stage W2 + b2
    {
        const float4* wg = reinterpret_cast<const float4*>(lW2);
        float4* ws = reinterpret_cast<float4*>(sW);
        for (int t = tid; t < EMB * EMB / 4; t += THREADS) ws[t] = wg[t];
        if (tid < EMB) sBias[tid] = lb2[tid];
    }
    __syncthreads();

    // ---- layer 2: relu(h1 @ W2 + b2) -> sB ----
#pragma unroll
    for (int i = 0; i < 8; ++i)
#pragma unroll
        for (int j = 0; j < 8; ++j) acc[i][j] = 0.0f;
    tile_mma<EMB, SH_STRIDE>(sA, sW, acc, r0, c0);
#pragma unroll
    for (int i = 0; i < 8; ++i)
#pragma unroll
        for (int j = 0; j < 8; ++j)
            sB[(r0 + i) * SH_STRIDE + c0 + j] = fmaxf(acc[i][j] + sBias[c0 + j], 0.0f);
    __syncthreads();

    // stage W3 + b3
    {
        const float4* wg = reinterpret_cast<const float4*>(lW3);
        float4* ws = reinterpret_cast<float4*>(sW);
        for (int t = tid; t < EMB * EMB / 4; t += THREADS) ws[t] = wg[t];
        if (tid < EMB) sBias[tid] = lb3[tid];
    }
    __syncthreads();

    // ---- layer 3: h2 @ W3 + b3 (no relu) -> sA (safe: sA no longer read) ----
#pragma unroll
    for (int i = 0; i < 8; ++i)
#pragma unroll
        for (int j = 0; j < 8; ++j) acc[i][j] = 0.0f;
    tile_mma<EMB, SH_STRIDE>(sB, sW, acc, r0, c0);
#pragma unroll
    for (int i = 0; i < 8; ++i)
#pragma unroll
        for (int j = 0; j < 8; ++j)
            sA[(r0 + i) * SH_STRIDE + c0 + j] = acc[i][j] + sBias[c0 + j];
    __syncthreads();

    // ---- in-CTA segment reduction (index is globally sorted) ----
    if (tid < EMB) {
        const int col = tid;
        int cur = sIdx[0];
        float s = 0.0f;
#pragma unroll 4
        for (int r = 0; r < TM; ++r) {
            int idx = sIdx[r];
            if (idx != cur) {
                atomicAdd(&g_agg[(long long)cur * EMB + col], s);
                s = 0.0f;
                cur = idx;
            }
            s += sA[r * SH_STRIDE + col];
        }
        atomicAdd(&g_agg[(long long)cur * EMB + col], s);
    }
}

__global__ __launch_bounds__(128)
void global_mlp_kernel(const float* __restrict__ gW1, const float* __restrict__ gb1,
                       const float* __restrict__ gW2, const float* __restrict__ gb2,
                       const float* __restrict__ gW3, const float* __restrict__ gb3,
                       float* __restrict__ out) {
    __shared__ float sIn[EMB];
    __shared__ float sH[EMB];
    const int tid = threadIdx.x;
    const int seg = blockIdx.x;

    sIn[tid] = g_agg[seg * EMB + tid];
    __syncthreads();

    // layer g1
    float acc = gb1[tid];
#pragma unroll 8
    for (int k = 0; k < EMB; ++k) acc += sIn[k] * gW1[k * EMB + tid];
    sH[tid] = fmaxf(acc, 0.0f);
    __syncthreads();

    // layer g2 (write back into sIn; all sIn reads finished before this barrier)
    acc = gb2[tid];
#pragma unroll 8
    for (int k = 0; k < EMB; ++k) acc += sH[k] * gW2[k * EMB + tid];
    __syncthreads();
    sIn[tid] = fmaxf(acc, 0.0f);
    __syncthreads();

    // scores + log_softmax (warp 0)
    if (tid < NCAND) {
        float sc = gb3[tid];
#pragma unroll 8
        for (int k = 0; k < EMB; ++k) sc += sIn[k] * gW3[k * NCAND + tid];
        float m = sc;
#pragma unroll
        for (int o = 16; o > 0; o >>= 1) m = fmaxf(m, __shfl_xor_sync(0xffffffffu, m, o));
        float e = expf(sc - m);
        float ssum = e;
#pragma unroll
        for (int o = 16; o > 0; o >>= 1) ssum += __shfl_xor_sync(0xffffffffu, ssum, o);
        out[seg * NCAND + tid] = sc - m - logf(ssum);
    }
}

extern "C" void kernel_launch(void* const* d_in, const int* in_sizes, int n_in,
                              void* d_out, int out_size) {
    const float* x     = (const float*)d_in[0];
    const int*   index = (const int*)d_in[1];
    const float* lW1 = (const float*)d_in[2];
    const float* lb1 = (const float*)d_in[3];
    const float* lW2 = (const float*)d_in[4];
    const float* lb2 = (const float*)d_in[5];
    const float* lW3 = (const float*)d_in[6];
    const float* lb3 = (const float*)d_in[7];
    const float* gW1 = (const float*)d_in[8];
    const float* gb1 = (const float*)d_in[9];
    const float* gW2 = (const float*)d_in[10];
    const float* gb2 = (const float*)d_in[11];
    const float* gW3 = (const float*)d_in[12];
    const float* gb3 = (const float*)d_in[13];
    float* out = (float*)d_out;

    cudaFuncSetAttribute(local_mlp_kernel,
                         cudaFuncAttributeMaxDynamicSharedMemorySize, SMEM_BYTES);

    zero_agg_kernel<<<(NSEG * EMB + 255) / 256, 256>>>();
    local_mlp_kernel<<<NVOT / TM, THREADS, SMEM_BYTES>>>(x, index,
                                                         lW1, lb1, lW2, lb2, lW3, lb3);
    global_mlp_kernel<<<NSEG, 128>>>(gW1, gb1, gW2, gb2, gW3, gb3, out);
}

// round 5
// speedup vs baseline: 2.1606x; 2.1606x over previous
#include <cuda_runtime.h>
#include <cuda_bf16.h>
#include <cstdint>
#include <cstring>
#include <math.h>

#define NSEG   4096
#define NVOT   1048576
#define NCAND  32
#define EMB    128
#define TILE_M 64
#define NTILES (NVOT / TILE_M)   // 16384

// 256B-pitch shared-tile swizzle: XOR 16B-unit index with row low bits
#define SWB(o) ((o) ^ (((o) >> 4) & 0x70))

// ------------------------------------------------------------------
// Device scratch (allocation-free rule: __device__ globals)
// ------------------------------------------------------------------
__device__ float g_agg[NSEG * EMB];
__device__ __nv_bfloat16 g_w1h[128 * 64],  g_w1l[128 * 64];
__device__ __nv_bfloat16 g_w2h[128 * 128], g_w2l[128 * 128];
__device__ __nv_bfloat16 g_w3h[128 * 128], g_w3l[128 * 128];

// ------------------------------------------------------------------
// PTX helpers (sm_80-era: legal in compute_103 PTX)
// ------------------------------------------------------------------
__device__ __forceinline__ uint32_t smem_u32(const void* p) {
    uint32_t a;
    asm("{ .reg .u64 t; cvta.to.shared.u64 t, %1; cvt.u32.u64 %0, t; }" : "=r"(a) : "l"(p));
    return a;
}
__device__ __forceinline__ void ldsm4(uint32_t r[4], uint32_t addr) {
    asm volatile("ldmatrix.sync.aligned.m8n8.x4.shared.b16 {%0,%1,%2,%3}, [%4];"
                 : "=r"(r[0]), "=r"(r[1]), "=r"(r[2]), "=r"(r[3]) : "r"(addr));
}
__device__ __forceinline__ void mma16816(float c[4], const uint32_t a[4], const uint32_t b[2]) {
    asm volatile("mma.sync.aligned.m16n8k16.row.col.f32.bf16.bf16.f32 "
                 "{%0,%1,%2,%3}, {%4,%5,%6,%7}, {%8,%9}, {%0,%1,%2,%3};"
                 : "+f"(c[0]), "+f"(c[1]), "+f"(c[2]), "+f"(c[3])
                 : "r"(a[0]), "r"(a[1]), "r"(a[2]), "r"(a[3]), "r"(b[0]), "r"(b[1]));
}
__device__ __forceinline__ uint32_t packbf(__nv_bfloat16 a, __nv_bfloat16 b) {
    __nv_bfloat162 t = __halves2bfloat162(a, b);
    uint32_t r; memcpy(&r, &t, 4); return r;
}

// ------------------------------------------------------------------
// Weight prep: transpose to [n][k], split into bf16 hi/lo
// ------------------------------------------------------------------
__global__ void prep_weights(const float* __restrict__ lW1,
                             const float* __restrict__ lW2,
                             const float* __restrict__ lW3) {
    int i = blockIdx.x * 256 + threadIdx.x;
    float v; __nv_bfloat16 *hp, *lp;
    if (i < 8192)       { int n = i >> 6, k = i & 63;
                          v = (k < 32) ? lW1[k * 128 + n] : 0.0f; hp = g_w1h + i; lp = g_w1l + i; }
    else if (i < 24576) { int e = i - 8192;  int n = e >> 7, k = e & 127;
                          v = lW2[k * 128 + n]; hp = g_w2h + e; lp = g_w2l + e; }
    else if (i < 40960) { int e = i - 24576; int n = e >> 7, k = e & 127;
                          v = lW3[k * 128 + n]; hp = g_w3h + e; lp = g_w3l + e; }
    else return;
    __nv_bfloat16 h = __float2bfloat16(v);
    *hp = h;
    *lp = __float2bfloat16(v - __bfloat162float(h));
}

__global__ void zero_agg_kernel() {
    int i = blockIdx.x * blockDim.x + threadIdx.x;
    if (i < NSEG * EMB) g_agg[i] = 0.0f;
}

// ------------------------------------------------------------------
// Local MLP: persistent HMMA kernel
// smem layout (byte offsets from 1024-aligned base)
// ------------------------------------------------------------------
#define OFF_W1H 0          /* [128][pitch 80B], k<32 used */
#define OFF_W1L 10240
#define OFF_W2H 20480      /* [128][256B] swizzled */
#define OFF_W2L 53248
#define OFF_W3H 86016
#define OFF_W3L 118784
#define OFF_P0H 151552     /* act buf 0 hi: [64][256B] swizzled */
#define OFF_P0L 167936
#define OFF_P1H 184320     /* act buf 1 hi; also fp32 reduce buf [64][132] */
#define OFF_P1L 200704
#define OFF_B1  218112
#define OFF_B2  218624
#define OFF_B3  219136
#define OFF_IDX 219648
#define DYN_BYTES (219904 + 1024)

// 3-pass (AhWh + AhWl + AlWh) GEMM: M=64 x N=128 x K=16*KSTEPS
template<int KSTEPS, bool ISW1>
__device__ __forceinline__ void gemm3(uint32_t aH, uint32_t aL,
                                      uint32_t wH, uint32_t wL,
                                      float acc[2][4][4], int wm, int wn, int lane) {
    const int r  = lane & 7;
    const int hs = (lane >> 3) & 1;
    const int qs = (lane >> 4) & 1;
    const int am0 = (wm + r + hs * 8) * 256;
    const int am1 = am0 + 16 * 256;
    const int bn0 = wn + r + qs * 8;
    const int bn1 = bn0 + 16;

#pragma unroll 1
    for (int pass = 0; pass < 3; ++pass) {
        const uint32_t aB = (pass == 2) ? aL : aH;
        const uint32_t wB = (pass == 1) ? wL : wH;
#pragma unroll
        for (int ks = 0; ks < KSTEPS; ++ks) {
            const int ka = (ks * 16 + qs * 8) * 2;
            const int kb = (ks * 16 + hs * 8) * 2;
            uint32_t a0[4], a1[4], bq0[4], bq1[4];
            ldsm4(a0, aB + SWB(am0 + ka));
            ldsm4(a1, aB + SWB(am1 + ka));
            if (ISW1) {
                ldsm4(bq0, wB + bn0 * 80 + kb);
                ldsm4(bq1, wB + bn1 * 80 + kb);
            } else {
                ldsm4(bq0, wB + SWB(bn0 * 256 + kb));
                ldsm4(bq1, wB + SWB(bn1 * 256 + kb));
            }
            mma16816(acc[0][0], a0, bq0 + 0);
            mma16816(acc[0][1], a0, bq0 + 2);
            mma16816(acc[0][2], a0, bq1 + 0);
            mma16816(acc[0][3], a0, bq1 + 2);
            mma16816(acc[1][0], a1, bq0 + 0);
            mma16816(acc[1][1], a1, bq0 + 2);
            mma16816(acc[1][2], a1, bq1 + 0);
            mma16816(acc[1][3], a1, bq1 + 2);
        }
    }
}

__device__ __forceinline__ void zacc(float acc[2][4][4]) {
#pragma unroll
    for (int i = 0; i < 2; ++i)
#pragma unroll
        for (int j = 0; j < 4; ++j)
#pragma unroll
            for (int q = 0; q < 4; ++q) acc[i][j][q] = 0.0f;
}

// bias + relu + hi/lo split -> swizzled bf16 act buffers
__device__ __forceinline__ void epi_relu(float acc[2][4][4], char* wb,
                                         uint32_t offH, uint32_t offL,
                                         const float* bias, int wm, int wn, int lane) {
    const int mr  = wm + (lane >> 2);
    const int nc0 = wn + 2 * (lane & 3);
#pragma unroll
    for (int mt = 0; mt < 2; ++mt)
#pragma unroll
        for (int nt = 0; nt < 4; ++nt) {
            const int n = nc0 + nt * 8;
            const float b0 = bias[n], b1 = bias[n + 1];
            const float* c = acc[mt][nt];
#pragma unroll
            for (int h = 0; h < 2; ++h) {
                const int m = mr + mt * 16 + h * 8;
                float v0 = fmaxf(c[2 * h]     + b0, 0.0f);
                float v1 = fmaxf(c[2 * h + 1] + b1, 0.0f);
                __nv_bfloat16 h0 = __float2bfloat16(v0), h1 = __float2bfloat16(v1);
                uint32_t off = (uint32_t)SWB(m * 256 + n * 2);
                *(uint32_t*)(wb + offH + off) = packbf(h0, h1);
                *(uint32_t*)(wb + offL + off) =
                    packbf(__float2bfloat16(v0 - __bfloat162float(h0)),
                           __float2bfloat16(v1 - __bfloat162float(h1)));
            }
        }
}

// bias (no relu) -> fp32 reduce buffer [64][132]
__device__ __forceinline__ void epi_out(float acc[2][4][4], float* red,
                                        const float* bias, int wm, int wn, int lane) {
    const int mr  = wm + (lane >> 2);
    const int nc0 = wn + 2 * (lane & 3);
#pragma unroll
    for (int mt = 0; mt < 2; ++mt)
#pragma unroll
        for (int nt = 0; nt < 4; ++nt) {
            const int n = nc0 + nt * 8;
            const float b0 = bias[n], b1 = bias[n + 1];
            const float* c = acc[mt][nt];
#pragma unroll
            for (int h = 0; h < 2; ++h) {
                const int m = mr + mt * 16 + h * 8;
                float2 v = make_float2(c[2 * h] + b0, c[2 * h + 1] + b1);
                *(float2*)(red + m * 132 + n) = v;
            }
        }
}

__global__ __launch_bounds__(256, 1)
void local_mlp_hmma(const float* __restrict__ x, const int* __restrict__ index,
                    const float* __restrict__ lb1, const float* __restrict__ lb2,
                    const float* __restrict__ lb3) {
    extern __shared__ char dsm[];
    char* wb = (char*)(((uintptr_t)dsm + 1023) & ~(uintptr_t)1023);
    const uint32_t wb32 = smem_u32(wb);

    const int tid  = threadIdx.x;
    const int wid  = tid >> 5;
    const int lane = tid & 31;
    const int wm = (wid & 1) * 32;
    const int wn = (wid >> 1) * 32;

    // ---- stage weights once per CTA ----
    // W2/W3 hi/lo: [n][k] -> swizzled 256B-pitch tiles, 16B chunks
    for (int e = tid; e < 2048; e += 256) {
        int n = e >> 4, k0 = (e & 15) * 8;
        uint32_t off = (uint32_t)SWB(n * 256 + k0 * 2);
        *(uint4*)(wb + OFF_W2H + off) = *(const uint4*)(g_w2h + n * 128 + k0);
        *(uint4*)(wb + OFF_W2L + off) = *(const uint4*)(g_w2l + n * 128 + k0);
        *(uint4*)(wb + OFF_W3H + off) = *(const uint4*)(g_w3h + n * 128 + k0);
        *(uint4*)(wb + OFF_W3L + off) = *(const uint4*)(g_w3l + n * 128 + k0);
    }
    // W1 hi/lo: [n][k<32] pitch 80B (bank-clean without swizzle), 8B chunks
    for (int e = tid; e < 1024; e += 256) {
        int n = e >> 3, k0 = (e & 7) * 4;
        uint32_t off = (uint32_t)(n * 80 + k0 * 2);
        *(uint2*)(wb + OFF_W1H + off) = *(const uint2*)(g_w1h + n * 64 + k0);
        *(uint2*)(wb + OFF_W1L + off) = *(const uint2*)(g_w1l + n * 64 + k0);
    }
    float* sB1 = (float*)(wb + OFF_B1);
    float* sB2 = (float*)(wb + OFF_B2);
    float* sB3 = (float*)(wb + OFF_B3);
    int*   sIdx = (int*)(wb + OFF_IDX);
    float* red  = (float*)(wb + OFF_P1H);
    if (tid < 128) { sB1[tid] = lb1[tid]; sB2[tid] = lb2[tid]; sB3[tid] = lb3[tid]; }
    __syncthreads();

    const uint32_t P0H = wb32 + OFF_P0H, P0L = wb32 + OFF_P0L;
    const uint32_t P1H = wb32 + OFF_P1H, P1L = wb32 + OFF_P1L;
    const uint32_t W1H = wb32 + OFF_W1H, W1L = wb32 + OFF_W1L;
    const uint32_t W2H = wb32 + OFF_W2H, W2L = wb32 + OFF_W2L;
    const uint32_t W3H = wb32 + OFF_W3H, W3L = wb32 + OFF_W3L;

    float acc[2][4][4];

    for (int t = blockIdx.x; t < NTILES; t += gridDim.x) {
        const size_t v0 = (size_t)t * TILE_M;

        // ---- stage x -> P0 (bf16 hi/lo, swizzled); indices ----
        {
            const int m  = tid >> 2;
            const int c8 = (tid & 3) * 8;
            const float4* xr = (const float4*)(x + (v0 + m) * NCAND + c8);
            float4 f0 = xr[0], f1 = xr[1];
            __nv_bfloat16 h0 = __float2bfloat16(f0.x), h1 = __float2bfloat16(f0.y);
            __nv_bfloat16 h2 = __float2bfloat16(f0.z), h3 = __float2bfloat16(f0.w);
            __nv_bfloat16 h4 = __float2bfloat16(f1.x), h5 = __float2bfloat16(f1.y);
            __nv_bfloat16 h6 = __float2bfloat16(f1.z), h7 = __float2bfloat16(f1.w);
            uint4 hi = make_uint4(packbf(h0, h1), packbf(h2, h3), packbf(h4, h5), packbf(h6, h7));
            uint4 lo = make_uint4(
                packbf(__float2bfloat16(f0.x - __bfloat162float(h0)), __float2bfloat16(f0.y - __bfloat162float(h1))),
                packbf(__float2bfloat16(f0.z - __bfloat162float(h2)), __float2bfloat16(f0.w - __bfloat162float(h3))),
                packbf(__float2bfloat16(f1.x - __bfloat162float(h4)), __float2bfloat16(f1.y - __bfloat162float(h5))),
                packbf(__float2bfloat16(f1.z - __bfloat162float(h6)), __float2bfloat16(f1.w - __bfloat162float(h7))));
            uint32_t off = (uint32_t)SWB(m * 256 + c8 * 2);
            *(uint4*)(wb + OFF_P0H + off) = hi;
            *(uint4*)(wb + OFF_P0L + off) = lo;
            if (tid < TILE_M) sIdx[tid] = index[v0 + tid];
        }
        __syncthreads();

        // ---- L1: relu(x @ W1 + b1) -> P1 ----
        zacc(acc);
        gemm3<2, true>(P0H, P0L, W1H, W1L, acc, wm, wn, lane);
        epi_relu(acc, wb, OFF_P1H, OFF_P1L, sB1, wm, wn, lane);
        __syncthreads();

        // ---- L2: relu(h1 @ W2 + b2) -> P0 ----
        zacc(acc);
        gemm3<8, false>(P1H, P1L, W2H, W2L, acc, wm, wn, lane);
        epi_relu(acc, wb, OFF_P0H, OFF_P0L, sB2, wm, wn, lane);
        __syncthreads();

        // ---- L3: h2 @ W3 + b3 -> red (fp32) ----
        zacc(acc);
        gemm3<8, false>(P0H, P0L, W3H, W3L, acc, wm, wn, lane);
        epi_out(acc, red, sB3, wm, wn, lane);
        __syncthreads();

        // ---- sorted-segment reduce -> global atomics ----
        if (tid < 128) {
            const int col = tid;
            int cur = sIdx[0];
            float s = 0.0f;
#pragma unroll 4
            for (int r = 0; r < TILE_M; ++r) {
                int ix = sIdx[r];
                if (ix != cur) {
                    atomicAdd(&g_agg[cur * EMB + col], s);
                    s = 0.0f; cur = ix;
                }
                s += red[r * 132 + col];
            }
            atomicAdd(&g_agg[cur * EMB + col], s);
        }
        __syncthreads();
    }
}

// ------------------------------------------------------------------
// Global MLP: 128 CTAs x 32 segments, weights staged in smem
// ------------------------------------------------------------------
#define GDYN ((16384 + 16384 + 4096 + 3 * 128) * 4)

__global__ __launch_bounds__(128, 1)
void global_mlp_kernel(const float* __restrict__ gW1, const float* __restrict__ gb1,
                       const float* __restrict__ gW2, const float* __restrict__ gb2,
                       const float* __restrict__ gW3, const float* __restrict__ gb3,
                       float* __restrict__ out) {
    extern __shared__ float gsm[];
    float* sW1 = gsm;
    float* sW2 = sW1 + 16384;
    float* sW3 = sW2 + 16384;
    float* sIn = sW3 + 4096;
    float* sH  = sIn + 128;
    float* sG  = sH + 128;

    const int tid = threadIdx.x;
    for (int i = tid; i < 4096; i += 128) {
        ((float4*)sW1)[i] = ((const float4*)gW1)[i];
        ((float4*)sW2)[i] = ((const float4*)gW2)[i];
    }
    for (int i = tid; i < 1024; i += 128)
        ((float4*)sW3)[i] = ((const float4*)gW3)[i];
    const float b1 = gb1[tid], b2 = gb2[tid];
    const float b3 = (tid < NCAND) ? gb3[tid] : 0.0f;
    __syncthreads();

    const int seg0 = blockIdx.x * 32;
    for (int s = 0; s < 32; ++s) {
        const int seg = seg0 + s;
        sIn[tid] = g_agg[seg * EMB + tid];
        __syncthreads();

        float a1 = b1;
#pragma unroll 8
        for (int k = 0; k < EMB; ++k) a1 += sIn[k] * sW1[k * EMB + tid];
        sH[tid] = fmaxf(a1, 0.0f);
        __syncthreads();

        float a2 = b2;
#pragma unroll 8
        for (int k = 0; k < EMB; ++k) a2 += sH[k] * sW2[k * EMB + tid];
        sG[tid] = fmaxf(a2, 0.0f);
        __syncthreads();

        if (tid < NCAND) {
            float sc = b3;
#pragma unroll 8
            for (int k = 0; k < EMB; ++k) sc += sG[k] * sW3[k * NCAND + tid];
            float m = sc;
#pragma unroll
            for (int o = 16; o > 0; o >>= 1) m = fmaxf(m, __shfl_xor_sync(0xffffffffu, m, o));
            float e = expf(sc - m);
            float ssum = e;
#pragma unroll
            for (int o = 16; o > 0; o >>= 1) ssum += __shfl_xor_sync(0xffffffffu, ssum, o);
            out[seg * NCAND + tid] = sc - m - logf(ssum);
        }
        __syncthreads();
    }
}

extern "C" void kernel_launch(void* const* d_in, const int* in_sizes, int n_in,
                              void* d_out, int out_size) {
    const float* x     = (const float*)d_in[0];
    const int*   index = (const int*)d_in[1];
    const float* lW1 = (const float*)d_in[2];
    const float* lb1 = (const float*)d_in[3];
    const float* lW2 = (const float*)d_in[4];
    const float* lb2 = (const float*)d_in[5];
    const float* lW3 = (const float*)d_in[6];
    const float* lb3 = (const float*)d_in[7];
    const float* gW1 = (const float*)d_in[8];
    const float* gb1 = (const float*)d_in[9];
    const float* gW2 = (const float*)d_in[10];
    const float* gb2 = (const float*)d_in[11];
    const float* gW3 = (const float*)d_in[12];
    const float* gb3 = (const float*)d_in[13];
    float* out = (float*)d_out;

    cudaFuncSetAttribute(local_mlp_hmma,
                         cudaFuncAttributeMaxDynamicSharedMemorySize, DYN_BYTES);
    cudaFuncSetAttribute(global_mlp_kernel,
                         cudaFuncAttributeMaxDynamicSharedMemorySize, GDYN);

    prep_weights<<<160, 256>>>(lW1, lW2, lW3);
    zero_agg_kernel<<<(NSEG * EMB + 255) / 256, 256>>>();
    local_mlp_hmma<<<148, 256, DYN_BYTES>>>(x, index, lb1, lb2, lb3);
    global_mlp_kernel<<<128, 128, GDYN>>>(gW1, gb1, gW2, gb2, gW3, gb3, out);
}

// round 6
// speedup vs baseline: 2.5805x; 1.1944x over previous
#include <cuda_runtime.h>
#include <cuda_fp16.h>
#include <cstdint>
#include <cstring>
#include <math.h>

#define NSEG   4096
#define NVOT   1048576
#define NCAND  32
#define EMB    128
#define TILE_M 64
#define NTILES (NVOT / TILE_M)   // 16384

// 256B-pitch shared-tile swizzle: XOR 16B-unit index with row low bits
#define SWB(o) ((o) ^ (((o) >> 4) & 0x70))

// ------------------------------------------------------------------
// Device scratch (allocation-free rule: __device__ globals)
// ------------------------------------------------------------------
__device__ float g_agg[NSEG * EMB];
__device__ __half g_w1h[128 * 64],  g_w1l[128 * 64];
__device__ __half g_w2h[128 * 128], g_w2l[128 * 128];
__device__ __half g_w3h[128 * 128], g_w3l[128 * 128];

// ------------------------------------------------------------------
// PTX helpers (sm_80-era: legal in compute_103 PTX)
// ------------------------------------------------------------------
__device__ __forceinline__ uint32_t smem_u32(const void* p) {
    uint32_t a;
    asm("{ .reg .u64 t; cvta.to.shared.u64 t, %1; cvt.u32.u64 %0, t; }" : "=r"(a) : "l"(p));
    return a;
}
__device__ __forceinline__ void ldsm4(uint32_t r[4], uint32_t addr) {
    asm volatile("ldmatrix.sync.aligned.m8n8.x4.shared.b16 {%0,%1,%2,%3}, [%4];"
                 : "=r"(r[0]), "=r"(r[1]), "=r"(r[2]), "=r"(r[3]) : "r"(addr));
}
__device__ __forceinline__ void mma16816(float c[4], const uint32_t a[4], const uint32_t b[2]) {
    asm volatile("mma.sync.aligned.m16n8k16.row.col.f32.f16.f16.f32 "
                 "{%0,%1,%2,%3}, {%4,%5,%6,%7}, {%8,%9}, {%0,%1,%2,%3};"
                 : "+f"(c[0]), "+f"(c[1]), "+f"(c[2]), "+f"(c[3])
                 : "r"(a[0]), "r"(a[1]), "r"(a[2]), "r"(a[3]), "r"(b[0]), "r"(b[1]));
}
__device__ __forceinline__ uint32_t packh(__half a, __half b) {
    __half2 t = __halves2half2(a, b);
    uint32_t r; memcpy(&r, &t, 4); return r;
}

// ------------------------------------------------------------------
// Weight prep: transpose to [n][k], split into fp16 hi/lo
// ------------------------------------------------------------------
__global__ void prep_weights(const float* __restrict__ lW1,
                             const float* __restrict__ lW2,
                             const float* __restrict__ lW3) {
    int i = blockIdx.x * 256 + threadIdx.x;
    float v; __half *hp, *lp;
    if (i < 8192)       { int n = i >> 6, k = i & 63;
                          v = (k < 32) ? lW1[k * 128 + n] : 0.0f; hp = g_w1h + i; lp = g_w1l + i; }
    else if (i < 24576) { int e = i - 8192;  int n = e >> 7, k = e & 127;
                          v = lW2[k * 128 + n]; hp = g_w2h + e; lp = g_w2l + e; }
    else if (i < 40960) { int e = i - 24576; int n = e >> 7, k = e & 127;
                          v = lW3[k * 128 + n]; hp = g_w3h + e; lp = g_w3l + e; }
    else return;
    __half h = __float2half_rn(v);
    *hp = h;
    *lp = __float2half_rn(v - __half2float(h));
}

__global__ void zero_agg_kernel() {
    int i = blockIdx.x * blockDim.x + threadIdx.x;
    if (i < NSEG * EMB) g_agg[i] = 0.0f;
}

// ------------------------------------------------------------------
// Local MLP: persistent HMMA kernel, fp16 2-pass
// smem layout (byte offsets from 1024-aligned base)
// ------------------------------------------------------------------
#define OFF_W1H 0          /* [128][pitch 80B], k<32 used */
#define OFF_W1L 10240
#define OFF_W2H 20480      /* [128][256B] swizzled */
#define OFF_W2L 53248
#define OFF_W3H 86016
#define OFF_W3L 118784
#define OFF_P0  151552     /* act buf 0: [64][256B] swizzled fp16 */
#define OFF_P1  167936     /* act buf 1 */
#define OFF_RED 184320     /* fp32 reduce buf [64][132] */
#define OFF_B1  218112
#define OFF_B2  218624
#define OFF_B3  219136
#define OFF_IDX 219648
#define DYN_BYTES (219904 + 1024)

// 2-pass GEMM: D += A * (Wh + Wl).  M=64 x N=128 x K=16*KSTEPS.
// A fragments loaded once per kstep, reused for both W passes.
template<int KSTEPS, bool ISW1>
__device__ __forceinline__ void gemm2(uint32_t aB, uint32_t wH, uint32_t wL,
                                      float acc[2][4][4], int wm, int wn, int lane) {
    const int r  = lane & 7;
    const int hs = (lane >> 3) & 1;
    const int qs = (lane >> 4) & 1;
    const int am0 = (wm + r + hs * 8) * 256;
    const int am1 = am0 + 16 * 256;
    const int bn0 = wn + r + qs * 8;
    const int bn1 = bn0 + 16;

#pragma unroll
    for (int ks = 0; ks < KSTEPS; ++ks) {
        const int ka = (ks * 16 + qs * 8) * 2;
        const int kb = (ks * 16 + hs * 8) * 2;
        uint32_t a0[4], a1[4], bq0[4], bq1[4];
        ldsm4(a0, aB + SWB(am0 + ka));
        ldsm4(a1, aB + SWB(am1 + ka));
        // pass H
        if (ISW1) {
            ldsm4(bq0, wH + bn0 * 80 + kb);
            ldsm4(bq1, wH + bn1 * 80 + kb);
        } else {
            ldsm4(bq0, wH + SWB(bn0 * 256 + kb));
            ldsm4(bq1, wH + SWB(bn1 * 256 + kb));
        }
        mma16816(acc[0][0], a0, bq0 + 0);
        mma16816(acc[0][1], a0, bq0 + 2);
        mma16816(acc[0][2], a0, bq1 + 0);
        mma16816(acc[0][3], a0, bq1 + 2);
        mma16816(acc[1][0], a1, bq0 + 0);
        mma16816(acc[1][1], a1, bq0 + 2);
        mma16816(acc[1][2], a1, bq1 + 0);
        mma16816(acc[1][3], a1, bq1 + 2);
        // pass L (reuse A frags)
        if (ISW1) {
            ldsm4(bq0, wL + bn0 * 80 + kb);
            ldsm4(bq1, wL + bn1 * 80 + kb);
        } else {
            ldsm4(bq0, wL + SWB(bn0 * 256 + kb));
            ldsm4(bq1, wL + SWB(bn1 * 256 + kb));
        }
        mma16816(acc[0][0], a0, bq0 + 0);
        mma16816(acc[0][1], a0, bq0 + 2);
        mma16816(acc[0][2], a0, bq1 + 0);
        mma16816(acc[0][3], a0, bq1 + 2);
        mma16816(acc[1][0], a1, bq0 + 0);
        mma16816(acc[1][1], a1, bq0 + 2);
        mma16816(acc[1][2], a1, bq1 + 0);
        mma16816(acc[1][3], a1, bq1 + 2);
    }
}

__device__ __forceinline__ void zacc(float acc[2][4][4]) {
#pragma unroll
    for (int i = 0; i < 2; ++i)
#pragma unroll
        for (int j = 0; j < 4; ++j)
#pragma unroll
            for (int q = 0; q < 4; ++q) acc[i][j][q] = 0.0f;
}

// bias + relu -> fp16 act buffer (swizzled)
__device__ __forceinline__ void epi_relu(float acc[2][4][4], char* wb, uint32_t offD,
                                         const float* bias, int wm, int wn, int lane) {
    const int mr  = wm + (lane >> 2);
    const int nc0 = wn + 2 * (lane & 3);
#pragma unroll
    for (int mt = 0; mt < 2; ++mt)
#pragma unroll
        for (int nt = 0; nt < 4; ++nt) {
            const int n = nc0 + nt * 8;
            const float b0 = bias[n], b1 = bias[n + 1];
            const float* c = acc[mt][nt];
#pragma unroll
            for (int h = 0; h < 2; ++h) {
                const int m = mr + mt * 16 + h * 8;
                float v0 = fmaxf(c[2 * h]     + b0, 0.0f);
                float v1 = fmaxf(c[2 * h + 1] + b1, 0.0f);
                *(uint32_t*)(wb + offD + SWB((uint32_t)(m * 256 + n * 2))) =
                    packh(__float2half_rn(v0), __float2half_rn(v1));
            }
        }
}

// bias (no relu) -> fp32 reduce buffer [64][132]
__device__ __forceinline__ void epi_out(float acc[2][4][4], float* red,
                                        const float* bias, int wm, int wn, int lane) {
    const int mr  = wm + (lane >> 2);
    const int nc0 = wn + 2 * (lane & 3);
#pragma unroll
    for (int mt = 0; mt < 2; ++mt)
#pragma unroll
        for (int nt = 0; nt < 4; ++nt) {
            const int n = nc0 + nt * 8;
            const float b0 = bias[n], b1 = bias[n + 1];
            const float* c = acc[mt][nt];
#pragma unroll
            for (int h = 0; h < 2; ++h) {
                const int m = mr + mt * 16 + h * 8;
                *(float2*)(red + m * 132 + n) =
                    make_float2(c[2 * h] + b0, c[2 * h + 1] + b1);
            }
        }
}

__global__ __launch_bounds__(256, 1)
void local_mlp_hmma(const float* __restrict__ x, const int* __restrict__ index,
                    const float* __restrict__ lb1, const float* __restrict__ lb2,
                    const float* __restrict__ lb3) {
    extern __shared__ char dsm[];
    char* wb = (char*)(((uintptr_t)dsm + 1023) & ~(uintptr_t)1023);
    const uint32_t wb32 = smem_u32(wb);

    const int tid  = threadIdx.x;
    const int wid  = tid >> 5;
    const int lane = tid & 31;
    const int wm = (wid & 1) * 32;
    const int wn = (wid >> 1) * 32;

    // ---- stage weights once per CTA ----
    for (int e = tid; e < 2048; e += 256) {
        int n = e >> 4, k0 = (e & 15) * 8;
        uint32_t off = (uint32_t)SWB(n * 256 + k0 * 2);
        *(uint4*)(wb + OFF_W2H + off) = *(const uint4*)(g_w2h + n * 128 + k0);
        *(uint4*)(wb + OFF_W2L + off) = *(const uint4*)(g_w2l + n * 128 + k0);
        *(uint4*)(wb + OFF_W3H + off) = *(const uint4*)(g_w3h + n * 128 + k0);
        *(uint4*)(wb + OFF_W3L + off) = *(const uint4*)(g_w3l + n * 128 + k0);
    }
    for (int e = tid; e < 1024; e += 256) {
        int n = e >> 3, k0 = (e & 7) * 4;
        uint32_t off = (uint32_t)(n * 80 + k0 * 2);
        *(uint2*)(wb + OFF_W1H + off) = *(const uint2*)(g_w1h + n * 64 + k0);
        *(uint2*)(wb + OFF_W1L + off) = *(const uint2*)(g_w1l + n * 64 + k0);
    }
    float* sB1 = (float*)(wb + OFF_B1);
    float* sB2 = (float*)(wb + OFF_B2);
    float* sB3 = (float*)(wb + OFF_B3);
    int*   sIdx = (int*)(wb + OFF_IDX);
    float* red  = (float*)(wb + OFF_RED);
    if (tid < 128) { sB1[tid] = lb1[tid]; sB2[tid] = lb2[tid]; sB3[tid] = lb3[tid]; }
    __syncthreads();

    const uint32_t P0 = wb32 + OFF_P0, P1 = wb32 + OFF_P1;
    const uint32_t W1H = wb32 + OFF_W1H, W1L = wb32 + OFF_W1L;
    const uint32_t W2H = wb32 + OFF_W2H, W2L = wb32 + OFF_W2L;
    const uint32_t W3H = wb32 + OFF_W3H, W3L = wb32 + OFF_W3L;

    const int m  = tid >> 2;            // x staging coords
    const int c8 = (tid & 3) * 8;

    float acc[2][4][4];
    float4 f0, f1;
    int idxn = 0;

    // preload first tile's x + index
    {
        const size_t v0 = (size_t)blockIdx.x * TILE_M;
        const float4* xr = (const float4*)(x + (v0 + m) * NCAND + c8);
        f0 = xr[0]; f1 = xr[1];
        if (tid < TILE_M) idxn = index[v0 + tid];
    }

    for (int t = blockIdx.x; t < NTILES; t += gridDim.x) {
        // ---- stage x (registers) -> P0 fp16 swizzled; indices ----
        {
            uint4 hv = make_uint4(
                packh(__float2half_rn(f0.x), __float2half_rn(f0.y)),
                packh(__float2half_rn(f0.z), __float2half_rn(f0.w)),
                packh(__float2half_rn(f1.x), __float2half_rn(f1.y)),
                packh(__float2half_rn(f1.z), __float2half_rn(f1.w)));
            *(uint4*)(wb + OFF_P0 + SWB((uint32_t)(m * 256 + c8 * 2))) = hv;
            if (tid < TILE_M) sIdx[tid] = idxn;
        }
        __syncthreads();

        // ---- L1: relu(x @ W1 + b1) -> P1 ----
        zacc(acc);
        gemm2<2, true>(P0, W1H, W1L, acc, wm, wn, lane);
        epi_relu(acc, wb, OFF_P1, sB1, wm, wn, lane);
        __syncthreads();

        // ---- L2: relu(h1 @ W2 + b2) -> P0 ----
        zacc(acc);
        gemm2<8, false>(P1, W2H, W2L, acc, wm, wn, lane);
        epi_relu(acc, wb, OFF_P0, sB2, wm, wn, lane);
        __syncthreads();

        // ---- L3: h2 @ W3 + b3 -> red (fp32) ----
        zacc(acc);
        gemm2<8, false>(P0, W3H, W3L, acc, wm, wn, lane);
        epi_out(acc, red, sB3, wm, wn, lane);

        // ---- prefetch next tile's x/index (overlaps reduce) ----
        const int tn = t + gridDim.x;
        if (tn < NTILES) {
            const size_t v0n = (size_t)tn * TILE_M;
            const float4* xr = (const float4*)(x + (v0n + m) * NCAND + c8);
            f0 = xr[0]; f1 = xr[1];
            if (tid < TILE_M) idxn = index[v0n + tid];
        }
        __syncthreads();

        // ---- sorted-segment reduce -> global atomics ----
        if (tid < 128) {
            const int col = tid;
            int cur = sIdx[0];
            float s = 0.0f;
#pragma unroll 4
            for (int r = 0; r < TILE_M; ++r) {
                int ix = sIdx[r];
                if (ix != cur) {
                    atomicAdd(&g_agg[cur * EMB + col], s);
                    s = 0.0f; cur = ix;
                }
                s += red[r * 132 + col];
            }
            atomicAdd(&g_agg[cur * EMB + col], s);
        }
        __syncthreads();
    }
}

// ------------------------------------------------------------------
// Global MLP: 256 CTAs x 16 segments, smem weights, 4-way ILP
// ------------------------------------------------------------------
#define GDYN ((16384 + 16384 + 4096 + 3 * 128) * 4)

__global__ __launch_bounds__(128, 1)
void global_mlp_kernel(const float* __restrict__ gW1, const float* __restrict__ gb1,
                       const float* __restrict__ gW2, const float* __restrict__ gb2,
                       const float* __restrict__ gW3, const float* __restrict__ gb3,
                       float* __restrict__ out) {
    extern __shared__ float gsm[];
    float* sW1 = gsm;
    float* sW2 = sW1 + 16384;
    float* sW3 = sW2 + 16384;
    float* sIn = sW3 + 4096;
    float* sH  = sIn + 128;
    float* sG  = sH + 128;

    const int tid = threadIdx.x;
    for (int i = tid; i < 4096; i += 128) {
        ((float4*)sW1)[i] = ((const float4*)gW1)[i];
        ((float4*)sW2)[i] = ((const float4*)gW2)[i];
    }
    for (int i = tid; i < 1024; i += 128)
        ((float4*)sW3)[i] = ((const float4*)gW3)[i];
    const float b1 = gb1[tid], b2 = gb2[tid];
    const float b3 = (tid < NCAND) ? gb3[tid] : 0.0f;
    __syncthreads();

    const int seg0 = blockIdx.x * 16;
    for (int s = 0; s < 16; ++s) {
        const int seg = seg0 + s;
        sIn[tid] = g_agg[seg * EMB + tid];
        __syncthreads();

        float a0 = 0.f, a1 = 0.f, a2 = 0.f, a3 = 0.f;
#pragma unroll 8
        for (int k = 0; k < EMB; k += 4) {
            a0 += sIn[k]     * sW1[(k)     * EMB + tid];
            a1 += sIn[k + 1] * sW1[(k + 1) * EMB + tid];
            a2 += sIn[k + 2] * sW1[(k + 2) * EMB + tid];
            a3 += sIn[k + 3] * sW1[(k + 3) * EMB + tid];
        }
        sH[tid] = fmaxf((a0 + a1) + (a2 + a3) + b1, 0.0f);
        __syncthreads();

        a0 = a1 = a2 = a3 = 0.f;
#pragma unroll 8
        for (int k = 0; k < EMB; k += 4) {
            a0 += sH[k]     * sW2[(k)     * EMB + tid];
            a1 += sH[k + 1] * sW2[(k + 1) * EMB + tid];
            a2 += sH[k + 2] * sW2[(k + 2) * EMB + tid];
            a3 += sH[k + 3] * sW2[(k + 3) * EMB + tid];
        }
        sG[tid] = fmaxf((a0 + a1) + (a2 + a3) + b2, 0.0f);
        __syncthreads();

        if (tid < NCAND) {
            float c0 = 0.f, c1 = 0.f, c2 = 0.f, c3 = 0.f;
#pragma unroll 8
            for (int k = 0; k < EMB; k += 4) {
                c0 += sG[k]     * sW3[(k)     * NCAND + tid];
                c1 += sG[k + 1] * sW3[(k + 1) * NCAND + tid];
                c2 += sG[k + 2] * sW3[(k + 2) * NCAND + tid];
                c3 += sG[k + 3] * sW3[(k + 3) * NCAND + tid];
            }
            float sc = (c0 + c1) + (c2 + c3) + b3;
            float mx = sc;
#pragma unroll
            for (int o = 16; o > 0; o >>= 1) mx = fmaxf(mx, __shfl_xor_sync(0xffffffffu, mx, o));
            float e = expf(sc - mx);
            float ssum = e;
#pragma unroll
            for (int o = 16; o > 0; o >>= 1) ssum += __shfl_xor_sync(0xffffffffu, ssum, o);
            out[seg * NCAND + tid] = sc - mx - logf(ssum);
        }
        __syncthreads();
    }
}

extern "C" void kernel_launch(void* const* d_in, const int* in_sizes, int n_in,
                              void* d_out, int out_size) {
    const float* x     = (const float*)d_in[0];
    const int*   index = (const int*)d_in[1];
    const float* lW1 = (const float*)d_in[2];
    const float* lb1 = (const float*)d_in[3];
    const float* lW2 = (const float*)d_in[4];
    const float* lb2 = (const float*)d_in[5];
    const float* lW3 = (const float*)d_in[6];
    const float* lb3 = (const float*)d_in[7];
    const float* gW1 = (const float*)d_in[8];
    const float* gb1 = (const float*)d_in[9];
    const float* gW2 = (const float*)d_in[10];
    const float* gb2 = (const float*)d_in[11];
    const float* gW3 = (const float*)d_in[12];
    const float* gb3 = (const float*)d_in[13];
    float* out = (float*)d_out;

    cudaFuncSetAttribute(local_mlp_hmma,
                         cudaFuncAttributeMaxDynamicSharedMemorySize, DYN_BYTES);
    cudaFuncSetAttribute(global_mlp_kernel,
                         cudaFuncAttributeMaxDynamicSharedMemorySize, GDYN);

    prep_weights<<<160, 256>>>(lW1, lW2, lW3);
    zero_agg_kernel<<<(NSEG * EMB + 255) / 256, 256>>>();
    local_mlp_hmma<<<148, 256, DYN_BYTES>>>(x, index, lb1, lb2, lb3);
    global_mlp_kernel<<<256, 128, GDYN>>>(gW1, gb1, gW2, gb2, gW3, gb3, out);
}

// round 7
// speedup vs baseline: 4.8931x; 1.8961x over previous
#include <cuda_runtime.h>
#include <cuda_fp16.h>
#include <cstdint>
#include <cstring>
#include <math.h>

#define NSEG   4096
#define NVOT   1048576
#define NCAND  32
#define EMB    128
#define TILE_M 128
#define NTILES (NVOT / TILE_M)   // 8192

// 256B-pitch shared-tile swizzle: XOR 16B-unit index with row low bits
#define SWB(o) ((o) ^ (((o) >> 4) & 0x70))

// ------------------------------------------------------------------
// Device scratch (allocation-free rule: __device__ globals)
// ------------------------------------------------------------------
__device__ float g_agg[NSEG * EMB];
__device__ __half g_w1[128 * 64];
__device__ __half g_w2[128 * 128];
__device__ __half g_w3[128 * 128];

// ------------------------------------------------------------------
// PTX helpers (sm_80-era: legal in compute_103 PTX)
// ------------------------------------------------------------------
__device__ __forceinline__ uint32_t smem_u32(const void* p) {
    uint32_t a;
    asm("{ .reg .u64 t; cvta.to.shared.u64 t, %1; cvt.u32.u64 %0, t; }" : "=r"(a) : "l"(p));
    return a;
}
__device__ __forceinline__ void ldsm4(uint32_t r[4], uint32_t addr) {
    asm volatile("ldmatrix.sync.aligned.m8n8.x4.shared.b16 {%0,%1,%2,%3}, [%4];"
                 : "=r"(r[0]), "=r"(r[1]), "=r"(r[2]), "=r"(r[3]) : "r"(addr));
}
__device__ __forceinline__ void mma16816(float c[4], const uint32_t a[4], const uint32_t b[2]) {
    asm volatile("mma.sync.aligned.m16n8k16.row.col.f32.f16.f16.f32 "
                 "{%0,%1,%2,%3}, {%4,%5,%6,%7}, {%8,%9}, {%0,%1,%2,%3};"
                 : "+f"(c[0]), "+f"(c[1]), "+f"(c[2]), "+f"(c[3])
                 : "r"(a[0]), "r"(a[1]), "r"(a[2]), "r"(a[3]), "r"(b[0]), "r"(b[1]));
}
__device__ __forceinline__ uint32_t packh(__half a, __half b) {
    __half2 t = __halves2half2(a, b);
    uint32_t r; memcpy(&r, &t, 4); return r;
}

// ------------------------------------------------------------------
// Weight prep: transpose to [n][k], convert to fp16
// ------------------------------------------------------------------
__global__ void prep_weights(const float* __restrict__ lW1,
                             const float* __restrict__ lW2,
                             const float* __restrict__ lW3) {
    int i = blockIdx.x * 256 + threadIdx.x;
    if (i < 8192)       { int n = i >> 6, k = i & 63;
                          g_w1[i] = __float2half_rn((k < 32) ? lW1[k * 128 + n] : 0.0f); }
    else if (i < 24576) { int e = i - 8192;  int n = e >> 7, k = e & 127;
                          g_w2[e] = __float2half_rn(lW2[k * 128 + n]); }
    else if (i < 40960) { int e = i - 24576; int n = e >> 7, k = e & 127;
                          g_w3[e] = __float2half_rn(lW3[k * 128 + n]); }
}

__global__ void zero_agg_kernel() {
    int i = blockIdx.x * blockDim.x + threadIdx.x;
    if (i < NSEG * EMB) g_agg[i] = 0.0f;
}

// ------------------------------------------------------------------
// Local MLP: persistent HMMA kernel, fp16 single-pass, TILE_M=128
// smem layout (byte offsets from 1024-aligned base)
// ------------------------------------------------------------------
#define OFF_W1  0          /* [128][pitch 80B], k<32 used : 10240 */
#define OFF_W2  10240      /* [128][256B] swizzled : 32768 */
#define OFF_W3  43008
#define OFF_P0  75776      /* act buf 0: [128][256B] swizzled fp16 */
#define OFF_P1  108544     /* act buf 1 */
#define OFF_RED 141312     /* fp32 reduce buf [128][132] = 67584 */
#define OFF_B1  208896
#define OFF_B2  209408
#define OFF_B3  209920
#define OFF_IDX 210432     /* 128 ints */
#define DYN_BYTES (210944 + 1024)

// Single-pass GEMM: D += A * W.  M=128 x N=128 x K=16*KSTEPS.
// 8 warps: wm = (wid>>2)*64 (4 m16 frags each), wn = (wid&3)*32.
template<int KSTEPS, bool ISW1>
__device__ __forceinline__ void gemm1(uint32_t aB, uint32_t wB,
                                      float acc[4][4][4], int wm, int wn, int lane) {
    const int r  = lane & 7;
    const int hs = (lane >> 3) & 1;
    const int qs = (lane >> 4) & 1;
    int am[4];
#pragma unroll
    for (int f = 0; f < 4; ++f) am[f] = (wm + f * 16 + r + hs * 8) * 256;
    const int bn0 = wn + r + qs * 8;
    const int bn1 = bn0 + 16;

#pragma unroll
    for (int ks = 0; ks < KSTEPS; ++ks) {
        const int ka = (ks * 16 + qs * 8) * 2;
        const int kb = (ks * 16 + hs * 8) * 2;
        uint32_t a[4][4], bq0[4], bq1[4];
        if (ISW1) {
            ldsm4(bq0, wB + bn0 * 80 + kb);
            ldsm4(bq1, wB + bn1 * 80 + kb);
        } else {
            ldsm4(bq0, wB + SWB(bn0 * 256 + kb));
            ldsm4(bq1, wB + SWB(bn1 * 256 + kb));
        }
#pragma unroll
        for (int f = 0; f < 4; ++f) ldsm4(a[f], aB + SWB(am[f] + ka));
#pragma unroll
        for (int f = 0; f < 4; ++f) {
            mma16816(acc[f][0], a[f], bq0 + 0);
            mma16816(acc[f][1], a[f], bq0 + 2);
            mma16816(acc[f][2], a[f], bq1 + 0);
            mma16816(acc[f][3], a[f], bq1 + 2);
        }
    }
}

__device__ __forceinline__ void zacc(float acc[4][4][4]) {
#pragma unroll
    for (int i = 0; i < 4; ++i)
#pragma unroll
        for (int j = 0; j < 4; ++j)
#pragma unroll
            for (int q = 0; q < 4; ++q) acc[i][j][q] = 0.0f;
}

// bias + relu -> fp16 act buffer (swizzled)
__device__ __forceinline__ void epi_relu(float acc[4][4][4], char* wb, uint32_t offD,
                                         const float* bias, int wm, int wn, int lane) {
    const int mr  = wm + (lane >> 2);
    const int nc0 = wn + 2 * (lane & 3);
#pragma unroll
    for (int f = 0; f < 4; ++f)
#pragma unroll
        for (int nt = 0; nt < 4; ++nt) {
            const int n = nc0 + nt * 8;
            const float b0 = bias[n], b1 = bias[n + 1];
            const float* c = acc[f][nt];
#pragma unroll
            for (int h = 0; h < 2; ++h) {
                const int m = mr + f * 16 + h * 8;
                float v0 = fmaxf(c[2 * h]     + b0, 0.0f);
                float v1 = fmaxf(c[2 * h + 1] + b1, 0.0f);
                *(uint32_t*)(wb + offD + SWB((uint32_t)(m * 256 + n * 2))) =
                    packh(__float2half_rn(v0), __float2half_rn(v1));
            }
        }
}

// bias (no relu) -> fp32 reduce buffer [128][132]
__device__ __forceinline__ void epi_out(float acc[4][4][4], float* red,
                                        const float* bias, int wm, int wn, int lane) {
    const int mr  = wm + (lane >> 2);
    const int nc0 = wn + 2 * (lane & 3);
#pragma unroll
    for (int f = 0; f < 4; ++f)
#pragma unroll
        for (int nt = 0; nt < 4; ++nt) {
            const int n = nc0 + nt * 8;
            const float b0 = bias[n], b1 = bias[n + 1];
            const float* c = acc[f][nt];
#pragma unroll
            for (int h = 0; h < 2; ++h) {
                const int m = mr + f * 16 + h * 8;
                *(float2*)(red + m * 132 + n) =
                    make_float2(c[2 * h] + b0, c[2 * h + 1] + b1);
            }
        }
}

__global__ __launch_bounds__(256, 1)
void local_mlp_hmma(const float* __restrict__ x, const int* __restrict__ index,
                    const float* __restrict__ lb1, const float* __restrict__ lb2,
                    const float* __restrict__ lb3) {
    extern __shared__ char dsm[];
    char* wb = (char*)(((uintptr_t)dsm + 1023) & ~(uintptr_t)1023);
    const uint32_t wb32 = smem_u32(wb);

    const int tid  = threadIdx.x;
    const int wid  = tid >> 5;
    const int lane = tid & 31;
    const int wm = (wid >> 2) * 64;
    const int wn = (wid & 3) * 32;

    // ---- stage weights once per CTA ----
    for (int e = tid; e < 2048; e += 256) {     // W2/W3: 16B chunks
        int n = e >> 4, k0 = (e & 15) * 8;
        uint32_t off = (uint32_t)SWB(n * 256 + k0 * 2);
        *(uint4*)(wb + OFF_W2 + off) = *(const uint4*)(g_w2 + n * 128 + k0);
        *(uint4*)(wb + OFF_W3 + off) = *(const uint4*)(g_w3 + n * 128 + k0);
    }
    for (int e = tid; e < 1024; e += 256) {     // W1: pitch 80B, 8B chunks
        int n = e >> 3, k0 = (e & 7) * 4;
        *(uint2*)(wb + OFF_W1 + (uint32_t)(n * 80 + k0 * 2)) =
            *(const uint2*)(g_w1 + n * 64 + k0);
    }
    float* sB1 = (float*)(wb + OFF_B1);
    float* sB2 = (float*)(wb + OFF_B2);
    float* sB3 = (float*)(wb + OFF_B3);
    int*   sIdx = (int*)(wb + OFF_IDX);
    float* red  = (float*)(wb + OFF_RED);
    if (tid < 128) { sB1[tid] = lb1[tid]; sB2[tid] = lb2[tid]; sB3[tid] = lb3[tid]; }
    __syncthreads();

    const uint32_t P0 = wb32 + OFF_P0, P1 = wb32 + OFF_P1;
    const uint32_t W1 = wb32 + OFF_W1, W2 = wb32 + OFF_W2, W3 = wb32 + OFF_W3;

    // x staging coords: each thread handles half a row (16 floats)
    const int  xm  = tid >> 1;
    const int  xc  = (tid & 1) * 16;

    float acc[4][4][4];
    float4 f4[4];
    int idxn = 0;

    // preload first tile's x + index
    {
        const size_t v0 = (size_t)blockIdx.x * TILE_M;
        const float4* xr = (const float4*)(x + (v0 + xm) * NCAND + xc);
#pragma unroll
        for (int q = 0; q < 4; ++q) f4[q] = xr[q];
        if (tid < TILE_M) idxn = index[v0 + tid];
    }

    for (int t = blockIdx.x; t < NTILES; t += gridDim.x) {
        // ---- stage x (registers) -> P0 fp16 swizzled; indices ----
        {
            uint4 h0 = make_uint4(
                packh(__float2half_rn(f4[0].x), __float2half_rn(f4[0].y)),
                packh(__float2half_rn(f4[0].z), __float2half_rn(f4[0].w)),
                packh(__float2half_rn(f4[1].x), __float2half_rn(f4[1].y)),
                packh(__float2half_rn(f4[1].z), __float2half_rn(f4[1].w)));
            uint4 h1 = make_uint4(
                packh(__float2half_rn(f4[2].x), __float2half_rn(f4[2].y)),
                packh(__float2half_rn(f4[2].z), __float2half_rn(f4[2].w)),
                packh(__float2half_rn(f4[3].x), __float2half_rn(f4[3].y)),
                packh(__float2half_rn(f4[3].z), __float2half_rn(f4[3].w)));
            uint32_t base = (uint32_t)(xm * 256 + xc * 2);
            *(uint4*)(wb + OFF_P0 + SWB(base))      = h0;
            *(uint4*)(wb + OFF_P0 + SWB(base + 16)) = h1;
            if (tid < TILE_M) sIdx[tid] = idxn;
        }
        __syncthreads();

        // ---- L1: relu(x @ W1 + b1) -> P1 ----
        zacc(acc);
        gemm1<2, true>(P0, W1, acc, wm, wn, lane);
        epi_relu(acc, wb, OFF_P1, sB1, wm, wn, lane);
        __syncthreads();

        // ---- L2: relu(h1 @ W2 + b2) -> P0 ----
        zacc(acc);
        gemm1<8, false>(P1, W2, acc, wm, wn, lane);
        epi_relu(acc, wb, OFF_P0, sB2, wm, wn, lane);
        __syncthreads();

        // ---- L3: h2 @ W3 + b3 -> red (fp32) ----
        zacc(acc);
        gemm1<8, false>(P0, W3, acc, wm, wn, lane);
        epi_out(acc, red, sB3, wm, wn, lane);

        // ---- prefetch next tile's x/index (overlaps reduce) ----
        const int tn = t + gridDim.x;
        if (tn < NTILES) {
            const size_t v0n = (size_t)tn * TILE_M;
            const float4* xr = (const float4*)(x + (v0n + xm) * NCAND + xc);
#pragma unroll
            for (int q = 0; q < 4; ++q) f4[q] = xr[q];
            if (tid < TILE_M) idxn = index[v0n + tid];
        }
        __syncthreads();

        // ---- sorted-segment reduce (all 256 threads: 2 row-halves/col) ----
        {
            const int col   = tid & 127;
            const int rbase = (tid >> 7) * 64;
            int cur = sIdx[rbase];
            float s = 0.0f;
#pragma unroll 4
            for (int r = 0; r < 64; ++r) {
                int ix = sIdx[rbase + r];
                if (ix != cur) {
                    atomicAdd(&g_agg[cur * EMB + col], s);
                    s = 0.0f; cur = ix;
                }
                s += red[(rbase + r) * 132 + col];
            }
            atomicAdd(&g_agg[cur * EMB + col], s);
        }
        __syncthreads();
    }
}

// ------------------------------------------------------------------
// Global MLP: 4096 CTAs x 1 segment, weights via L1/L2, 4-way ILP
// ------------------------------------------------------------------
__global__ __launch_bounds__(128)
void global_mlp_kernel(const float* __restrict__ gW1, const float* __restrict__ gb1,
                       const float* __restrict__ gW2, const float* __restrict__ gb2,
                       const float* __restrict__ gW3, const float* __restrict__ gb3,
                       float* __restrict__ out) {
    __shared__ float sIn[EMB];
    __shared__ float sH[EMB];
    __shared__ float sG[EMB];
    const int tid = threadIdx.x;
    const int seg = blockIdx.x;

    sIn[tid] = g_agg[seg * EMB + tid];
    __syncthreads();

    float a0 = 0.f, a1 = 0.f, a2 = 0.f, a3 = 0.f;
#pragma unroll 8
    for (int k = 0; k < EMB; k += 4) {
        a0 += sIn[k]     * __ldg(&gW1[(k)     * EMB + tid]);
        a1 += sIn[k + 1] * __ldg(&gW1[(k + 1) * EMB + tid]);
        a2 += sIn[k + 2] * __ldg(&gW1[(k + 2) * EMB + tid]);
        a3 += sIn[k + 3] * __ldg(&gW1[(k + 3) * EMB + tid]);
    }
    sH[tid] = fmaxf((a0 + a1) + (a2 + a3) + __ldg(&gb1[tid]), 0.0f);
    __syncthreads();

    a0 = a1 = a2 = a3 = 0.f;
#pragma unroll 8
    for (int k = 0; k < EMB; k += 4) {
        a0 += sH[k]     * __ldg(&gW2[(k)     * EMB + tid]);
        a1 += sH[k + 1] * __ldg(&gW2[(k + 1) * EMB + tid]);
        a2 += sH[k + 2] * __ldg(&gW2[(k + 2) * EMB + tid]);
        a3 += sH[k + 3] * __ldg(&gW2[(k + 3) * EMB + tid]);
    }
    sG[tid] = fmaxf((a0 + a1) + (a2 + a3) + __ldg(&gb2[tid]), 0.0f);
    __syncthreads();

    if (tid < NCAND) {
        float c0 = 0.f, c1 = 0.f, c2 = 0.f, c3 = 0.f;
#pragma unroll 8
        for (int k = 0; k < EMB; k += 4) {
            c0 += sG[k]     * __ldg(&gW3[(k)     * NCAND + tid]);
            c1 += sG[k + 1] * __ldg(&gW3[(k + 1) * NCAND + tid]);
            c2 += sG[k + 2] * __ldg(&gW3[(k + 2) * NCAND + tid]);
            c3 += sG[k + 3] * __ldg(&gW3[(k + 3) * NCAND + tid]);
        }
        float sc = (c0 + c1) + (c2 + c3) + __ldg(&gb3[tid]);
        float mx = sc;
#pragma unroll
        for (int o = 16; o > 0; o >>= 1) mx = fmaxf(mx, __shfl_xor_sync(0xffffffffu, mx, o));
        float e = expf(sc - mx);
        float ssum = e;
#pragma unroll
        for (int o = 16; o > 0; o >>= 1) ssum += __shfl_xor_sync(0xffffffffu, ssum, o);
        out[seg * NCAND + tid] = sc - mx - logf(ssum);
    }
}

extern "C" void kernel_launch(void* const* d_in, const int* in_sizes, int n_in,
                              void* d_out, int out_size) {
    const float* x     = (const float*)d_in[0];
    const int*   index = (const int*)d_in[1];
    const float* lW1 = (const float*)d_in[2];
    const float* lb1 = (const float*)d_in[3];
    const float* lW2 = (const float*)d_in[4];
    const float* lb2 = (const float*)d_in[5];
    const float* lW3 = (const float*)d_in[6];
    const float* lb3 = (const float*)d_in[7];
    const float* gW1 = (const float*)d_in[8];
    const float* gb1 = (const float*)d_in[9];
    const float* gW2 = (const float*)d_in[10];
    const float* gb2 = (const float*)d_in[11];
    const float* gW3 = (const float*)d_in[12];
    const float* gb3 = (const float*)d_in[13];
    float* out = (float*)d_out;

    cudaFuncSetAttribute(local_mlp_hmma,
                         cudaFuncAttributeMaxDynamicSharedMemorySize, DYN_BYTES);

    prep_weights<<<160, 256>>>(lW1, lW2, lW3);
    zero_agg_kernel<<<(NSEG * EMB + 255) / 256, 256>>>();
    local_mlp_hmma<<<148, 256, DYN_BYTES>>>(x, index, lb1, lb2, lb3);
    global_mlp_kernel<<<NSEG, 128>>>(gW1, gb1, gW2, gb2, gW3, gb3, out);
}